// round 15
// baseline (speedup 1.0000x reference)
#include <cuda_runtime.h>
#include <cuda_bf16.h>
#include <cuda_fp16.h>
#include <math.h>

// ---------------------------------------------------------------------------
// GPT forward. All-fp16 tensor-core GEMMs (fp32 accumulate), fp32 elementwise.
// B=4, T=512, K=512, H=8, NB=4, VOCAB=32000. M = B*T = 2048 tokens.
//
// R15: 64-element K-chunks (halved per-chunk barrier/pipeline overhead),
// split-K reduction fused into LayerNorm. fp16 single-pass GEMMs, fused QKV,
// causal skip/truncate, split-K skinny GEMMs.
// ---------------------------------------------------------------------------

#define BATCH 4
#define SEQ   512
#define KD    512
#define HEADS 8
#define NBLK  4
#define VOCAB 32000
#define MTOK  (BATCH*SEQ)        // 2048
#define HK    (HEADS*KD)         // 4096
#define QKVN  (3*HK)             // 12288
#define FF    (4*KD)             // 2048
#define NBH   (BATCH*HEADS)      // 32

// fp32 scratch
__device__ float g_h  [MTOK*KD];
__device__ float g_att[NBH*SEQ*SEQ];      // scores; reused as split-K partials
// fp16 scratch
__device__ __align__(256) __half g_hf  [MTOK*KD];
__device__ __align__(256) __half g_wt  [(size_t)VOCAB*KD];
__device__ __align__(256) __half g_qkv [(size_t)MTOK*QKVN];
__device__ __align__(256) __half g_vt  [MTOK*HK];
__device__ __align__(256) __half g_as  [NBH*SEQ*SEQ];
__device__ __align__(256) __half g_yf  [MTOK*HK];
__device__ __align__(256) __half g_ff  [MTOK*FF];

// ---------------------------------------------------------------------------
// helpers
// ---------------------------------------------------------------------------
__device__ __forceinline__ unsigned smem_u32(const void* p) {
    unsigned r;
    asm("{ .reg .u64 t; cvta.to.shared.u64 t, %1; cvt.u32.u64 %0, t; }"
        : "=r"(r) : "l"(p));
    return r;
}
__device__ __forceinline__ void cp16(unsigned dst, const void* src) {
    asm volatile("cp.async.cg.shared.global [%0], [%1], 16;" :: "r"(dst), "l"(src));
}
#define CP_COMMIT() asm volatile("cp.async.commit_group;" ::: "memory")
#define CP_WAIT1()  asm volatile("cp.async.wait_group 1;" ::: "memory")

__device__ __forceinline__ void ldsm4(unsigned addr, unsigned& r0, unsigned& r1,
                                      unsigned& r2, unsigned& r3) {
    asm volatile("ldmatrix.sync.aligned.m8n8.x4.shared.b16 {%0,%1,%2,%3}, [%4];"
                 : "=r"(r0), "=r"(r1), "=r"(r2), "=r"(r3) : "r"(addr));
}
__device__ __forceinline__ void ldsm2(unsigned addr, unsigned& r0, unsigned& r1) {
    asm volatile("ldmatrix.sync.aligned.m8n8.x2.shared.b16 {%0,%1}, [%2];"
                 : "=r"(r0), "=r"(r1) : "r"(addr));
}
__device__ __forceinline__ void mma_f16(float* c, const unsigned* a, const unsigned* b) {
    asm volatile(
        "mma.sync.aligned.m16n8k16.row.col.f32.f16.f16.f32 "
        "{%0,%1,%2,%3},{%4,%5,%6,%7},{%8,%9},{%0,%1,%2,%3};"
        : "+f"(c[0]), "+f"(c[1]), "+f"(c[2]), "+f"(c[3])
        : "r"(a[0]), "r"(a[1]), "r"(a[2]), "r"(a[3]), "r"(b[0]), "r"(b[1]));
}

// SMEM stage: A 128 rows x 128B (64 fp16) + B same. Swizzle: 16B granule
// g' = g ^ (row & 7) within the 128B row.
#define STAGE_B   32768
#define A_BOFF    0
#define B_BOFF    16384
#define NSTAGE    3
#define GEMM_SMEM (NSTAGE*STAGE_B)   // 98304 bytes

// ---------------------------------------------------------------------------
// Pipelined fp16 GEMM, 64-k chunks.  A: [M][K] fp16.  B: [N][K] fp16.
// C = A * B^T.  EPI: 0 none, 1 +bias, 2 gelu(x+bias).  OUT: 0 fp32, 2 fp16.
// causal: 0 none, 1 tile-skip (bx>by), 2 K-trunc to (by+1)*128.
// Requires M%128==0, N%128==0, K%64==0.
// ---------------------------------------------------------------------------
template<int EPI, int OUT>
__global__ __launch_bounds__(256, 2)
void gemm_f16(const __half* __restrict__ A, const __half* __restrict__ B,
              const float* __restrict__ bias,
              float* __restrict__ C, __half* __restrict__ Ch,
              int M, int N, int K, int lda, int ldb, int ldc,
              long aO, long aI, long bO, long bI, long cO, long cI, int zdiv,
              int causal)
{
    extern __shared__ unsigned sm[];
    const unsigned sbase = smem_u32(sm);

    const int bx = blockIdx.x, by = blockIdx.y;
    if (causal == 1 && bx > by) return;
    if (causal == 2) K = min(K, (by + 1) * 128);

    const int z  = blockIdx.z;
    const int zb = z / zdiv, zh = z - zb * zdiv;
    const size_t aoff = (size_t)zb * aO + (size_t)zh * aI;
    const size_t boff = (size_t)zb * bO + (size_t)zh * bI;
    const size_t coff = (size_t)zb * cO + (size_t)zh * cI;
    A += aoff; B += boff;

    const int tid  = threadIdx.x;
    const int lane = tid & 31;
    const int warp = tid >> 5;
    const int g    = lane >> 2;
    const int tc   = lane & 3;
    const int wm   = (warp >> 2) * 64;
    const int wn   = (warp & 3) * 32;

    // loader: thread -> row tid>>1, half (tid&1): granules g = half*4 + j
    const int crow = tid >> 1;
    const int chalf = tid & 1;
    const __half* pA = A + (size_t)(by * 128 + crow) * lda + chalf * 32;
    const __half* pB = B + (size_t)(bx * 128 + crow) * ldb + chalf * 32;
    unsigned cdst[4];   // byte offsets within stage region
    #pragma unroll
    for (int j = 0; j < 4; j++) {
        const int gg = chalf * 4 + j;
        cdst[j] = (unsigned)(crow * 128 + ((gg ^ (crow & 7)) << 4));
    }

    // ldmatrix per-mf/nf byte bases + swizzle masks
    unsigned aB[4], bB[4];
    int aM[4], bM[4];
    {
        const int rowA = wm + (lane & 15);
        const int cxA  = lane >> 4;              // 0/1
        const int rowB = wn + (lane & 7);
        const int cxB  = (lane >> 3) & 1;
        #pragma unroll
        for (int mf = 0; mf < 4; mf++) {
            const int r = rowA + mf * 16;
            aB[mf] = (unsigned)(r * 128) + (unsigned)(cxA << 4);
            aM[mf] = r & 7;
        }
        #pragma unroll
        for (int nf = 0; nf < 4; nf++) {
            const int r = rowB + nf * 8;
            bB[nf] = (unsigned)(r * 128) + (unsigned)(cxB << 4);
            bM[nf] = r & 7;
        }
        // fold swizzle of the cx granule into the mask usage:
        // address(kpb) = base_row + (((2*kpb + cx) ^ (r&7)) << 4)
        // store base without the cx<<4 term; recompute per kpb below.
        #pragma unroll
        for (int mf = 0; mf < 4; mf++) aB[mf] -= (unsigned)((lane >> 4) << 4);
        #pragma unroll
        for (int nf = 0; nf < 4; nf++) bB[nf] -= (unsigned)(((lane >> 3) & 1) << 4);
    }
    const int cxA = lane >> 4;
    const int cxB = (lane >> 3) & 1;

    float acc[4][4][4];
    #pragma unroll
    for (int i = 0; i < 4; i++)
        #pragma unroll
        for (int j = 0; j < 4; j++)
            #pragma unroll
            for (int r = 0; r < 4; r++) acc[i][j][r] = 0.f;

    auto ISSUE = [&](int buf, int k0) {
        const unsigned sb = sbase + buf * STAGE_B;
        #pragma unroll
        for (int j = 0; j < 4; j++) {
            cp16(sb + A_BOFF + cdst[j], pA + k0 + j * 8);
            cp16(sb + B_BOFF + cdst[j], pB + k0 + j * 8);
        }
    };

    const int nc = K >> 6;

    ISSUE(0, 0);  CP_COMMIT();
    if (nc > 1) ISSUE(1, 64);
    CP_COMMIT();

    for (int i = 0; i < nc; i++) {
        CP_WAIT1();
        __syncthreads();

        if (i + 2 < nc) ISSUE((i + 2) % NSTAGE, (i + 2) * 64);
        CP_COMMIT();

        const unsigned stb = sbase + (i % NSTAGE) * STAGE_B;
        #pragma unroll
        for (int kpb = 0; kpb < 4; kpb++) {
            const int kg = 2 * kpb;
            unsigned Bf[4][2];
            #pragma unroll
            for (int nf = 0; nf < 4; nf++)
                ldsm2(stb + B_BOFF + bB[nf] + (unsigned)(((kg + cxB) ^ bM[nf]) << 4),
                      Bf[nf][0], Bf[nf][1]);
            #pragma unroll
            for (int mf = 0; mf < 4; mf++) {
                unsigned Aa[4];
                ldsm4(stb + A_BOFF + aB[mf] + (unsigned)(((kg + cxA) ^ aM[mf]) << 4),
                      Aa[0], Aa[1], Aa[2], Aa[3]);
                #pragma unroll
                for (int nf = 0; nf < 4; nf++)
                    mma_f16(acc[mf][nf], Aa, Bf[nf]);
            }
        }
    }

    // ---- epilogue ----
    #pragma unroll
    for (int mf = 0; mf < 4; mf++) {
        const int r0 = by * 128 + wm + mf * 16 + g;
        #pragma unroll
        for (int nf = 0; nf < 4; nf++) {
            const int col = bx * 128 + wn + nf * 8 + tc * 2;
            float c0 = acc[mf][nf][0], c1 = acc[mf][nf][1];
            float c2 = acc[mf][nf][2], c3 = acc[mf][nf][3];
            if (EPI >= 1) {
                const float b0v = bias[col], b1v = bias[col + 1];
                c0 += b0v; c1 += b1v; c2 += b0v; c3 += b1v;
            }
            if (EPI == 2) {
                c0 = 0.5f * c0 * (1.0f + erff(c0 * 0.7071067811865475f));
                c1 = 0.5f * c1 * (1.0f + erff(c1 * 0.7071067811865475f));
                c2 = 0.5f * c2 * (1.0f + erff(c2 * 0.7071067811865475f));
                c3 = 0.5f * c3 * (1.0f + erff(c3 * 0.7071067811865475f));
            }
            if (OUT == 0) {
                *(float2*)&C[coff + (size_t)r0 * ldc + col]       = make_float2(c0, c1);
                *(float2*)&C[coff + (size_t)(r0 + 8) * ldc + col] = make_float2(c2, c3);
            } else {
                *(__half2*)&Ch[coff + (size_t)r0 * ldc + col]       = __floats2half2_rn(c0, c1);
                *(__half2*)&Ch[coff + (size_t)(r0 + 8) * ldc + col] = __floats2half2_rn(c2, c3);
            }
        }
    }
}

// ---------------------------------------------------------------------------
// Fused split-K reduce + residual + LayerNorm.
// x = sum_{s<4} P[s*PS + i] + bias[col] + h[i]; h = LN(x)*w + b; hf = fp16(h).
// One block per token, 256 threads (KD=512 -> 2 elems/thread).
// ---------------------------------------------------------------------------
__global__ void ln_red_k(const float* __restrict__ P, long PS,
                         const float* __restrict__ bias,
                         float* __restrict__ h, __half* __restrict__ hf,
                         const float* __restrict__ w, const float* __restrict__ b)
{
    const int token = blockIdx.x;
    const size_t base = (size_t)token * KD;
    const int tid = threadIdx.x;
    float x0 = bias[tid]       + h[base + tid];
    float x1 = bias[tid + 256] + h[base + tid + 256];
    #pragma unroll
    for (int s = 0; s < 4; s++) {
        x0 += P[(size_t)s * PS + base + tid];
        x1 += P[(size_t)s * PS + base + tid + 256];
    }
    __shared__ float s1[256], s2[256];
    s1[tid] = x0 + x1;
    s2[tid] = x0 * x0 + x1 * x1;
    __syncthreads();
    for (int o = 128; o; o >>= 1) {
        if (tid < o) { s1[tid] += s1[tid + o]; s2[tid] += s2[tid + o]; }
        __syncthreads();
    }
    const float mean = s1[0] * (1.f / KD);
    const float var  = s2[0] * (1.f / KD) - mean * mean;
    const float r = rsqrtf(var + 1e-5f);
    const float y0 = (x0 - mean) * r * w[tid]       + b[tid];
    const float y1 = (x1 - mean) * r * w[tid + 256] + b[tid + 256];
    h[base + tid]        = y0;
    h[base + tid + 256]  = y1;
    hf[base + tid]       = __float2half(y0);
    hf[base + tid + 256] = __float2half(y1);
}

// Plain LayerNorm (no residual) for the final LN.
__global__ void ln_k(const float* __restrict__ src, float* __restrict__ h,
                     __half* __restrict__ hf,
                     const float* __restrict__ w, const float* __restrict__ b)
{
    const int token = blockIdx.x;
    const size_t base = (size_t)token * KD;
    const int tid = threadIdx.x;
    const float x0 = src[base + tid];
    const float x1 = src[base + tid + 256];
    __shared__ float s1[256], s2[256];
    s1[tid] = x0 + x1;
    s2[tid] = x0 * x0 + x1 * x1;
    __syncthreads();
    for (int o = 128; o; o >>= 1) {
        if (tid < o) { s1[tid] += s1[tid + o]; s2[tid] += s2[tid + o]; }
        __syncthreads();
    }
    const float mean = s1[0] * (1.f / KD);
    const float var  = s2[0] * (1.f / KD) - mean * mean;
    const float r = rsqrtf(var + 1e-5f);
    const float y0 = (x0 - mean) * r * w[tid]       + b[tid];
    const float y1 = (x1 - mean) * r * w[tid + 256] + b[tid + 256];
    h[base + tid]        = y0;
    h[base + tid + 256]  = y1;
    hf[base + tid]       = __float2half(y0);
    hf[base + tid + 256] = __float2half(y1);
}

// ---------------------------------------------------------------------------
// Weight transpose, fp16: src fp32 [K][N] -> dst fp16 [N][K].
// ---------------------------------------------------------------------------
__global__ void wconvh(const float* __restrict__ src, __half* __restrict__ dh,
                       int K, int N)
{
    __shared__ float t[32][33];
    const int k0 = blockIdx.x * 32, n0 = blockIdx.y * 32;
    const int tx = threadIdx.x, ty = threadIdx.y;
    #pragma unroll
    for (int r = 0; r < 4; r++)
        t[ty + r * 8][tx] = src[(size_t)(k0 + ty + r * 8) * N + n0 + tx];
    __syncthreads();
    #pragma unroll
    for (int r = 0; r < 4; r++)
        dh[(size_t)(n0 + ty + r * 8) * K + k0 + tx] = __float2half(t[tx][ty + r * 8]);
}

// Fused Wq/Wk/Wv transpose -> fp16 [QKVN][KD]. grid z picks src.
__global__ void wconv3h(const float* __restrict__ s0, const float* __restrict__ s1,
                        const float* __restrict__ s2, __half* __restrict__ dh)
{
    __shared__ float t[32][33];
    const float* src = (blockIdx.z == 0) ? s0 : (blockIdx.z == 1 ? s1 : s2);
    const int k0 = blockIdx.x * 32, n0 = blockIdx.y * 32;
    const int tx = threadIdx.x, ty = threadIdx.y;
    #pragma unroll
    for (int r = 0; r < 4; r++)
        t[ty + r * 8][tx] = src[(size_t)(k0 + ty + r * 8) * HK + n0 + tx];
    __syncthreads();
    const size_t rowoff = (size_t)blockIdx.z * HK;
    #pragma unroll
    for (int r = 0; r < 4; r++)
        dh[(rowoff + n0 + ty + r * 8) * KD + k0 + tx] = __float2half(t[tx][ty + r * 8]);
}

// ---------------------------------------------------------------------------
// V transpose per head from fp16 QKV buffer -> fp16 [(b*8+h)*512+d][t].
// ---------------------------------------------------------------------------
__global__ void vconvh(const __half* __restrict__ qv, __half* __restrict__ dh)
{
    __shared__ __half t[32][33];
    const int z = blockIdx.z, b = z >> 3, h = z & 7;
    const int t0 = blockIdx.x * 32, d0 = blockIdx.y * 32;
    const int tx = threadIdx.x, ty = threadIdx.y;
    #pragma unroll
    for (int r = 0; r < 4; r++) {
        const size_t si = (size_t)(b * SEQ + t0 + ty + r * 8) * QKVN
                        + 2 * HK + h * KD + d0 + tx;
        t[ty + r * 8][tx] = qv[si];
    }
    __syncthreads();
    #pragma unroll
    for (int r = 0; r < 4; r++) {
        const size_t o = ((size_t)z * KD + d0 + ty + r * 8) * SEQ + t0 + tx;
        dh[o] = t[tx][ty + r * 8];
    }
}

// ---------------------------------------------------------------------------
// Embedding + positional encoding.
// ---------------------------------------------------------------------------
__global__ void embed_k(const int* __restrict__ x, const float* __restrict__ W,
                        float* __restrict__ h, __half* __restrict__ hf)
{
    const int token = blockIdx.x;
    const int t  = token & (SEQ - 1);
    const int id = x[token];
    const int tid = threadIdx.x;
    #pragma unroll
    for (int u = 0; u < 2; u++) {
        const int c = tid + u * 256;
        const int j = c >> 1;
        const float ang = (float)t * expf(-(float)j * 0.07195578415606394f);
        const float p = (c & 1) ? cosf(ang) : sinf(ang);
        const float val = W[(size_t)id * KD + c] + p;
        const size_t o = (size_t)token * KD + c;
        h[o] = val;
        hf[o] = __float2half(val);
    }
}

// ---------------------------------------------------------------------------
// Causal softmax (scale folded), writes fp16 att.
// ---------------------------------------------------------------------------
__global__ void softmax_k(const float* __restrict__ att, __half* __restrict__ oh)
{
    const int q  = blockIdx.x;
    const int bh = blockIdx.y;
    const size_t base = ((size_t)bh * SEQ + q) * SEQ;
    const int tid = threadIdx.x;
    const float scale = 0.04419417382415922f;  // 1/sqrt(512)
    __shared__ float red[256];

    const float s0 = (tid       <= q) ? att[base + tid]       * scale : -3.4e38f;
    const float s1 = (tid + 256 <= q) ? att[base + tid + 256] * scale : -3.4e38f;
    red[tid] = fmaxf(s0, s1);
    __syncthreads();
    for (int o = 128; o; o >>= 1) {
        if (tid < o) red[tid] = fmaxf(red[tid], red[tid + o]);
        __syncthreads();
    }
    const float m = red[0];
    __syncthreads();
    const float v0 = (tid       <= q) ? expf(s0 - m) : 0.f;
    const float v1 = (tid + 256 <= q) ? expf(s1 - m) : 0.f;
    red[tid] = v0 + v1;
    __syncthreads();
    for (int o = 128; o; o >>= 1) {
        if (tid < o) red[tid] += red[tid + o];
        __syncthreads();
    }
    const float inv = 1.0f / red[0];
    oh[base + tid]       = __float2half(v0 * inv);
    oh[base + tid + 256] = __float2half(v1 * inv);
}

// ---------------------------------------------------------------------------
// Host-side launcher
// ---------------------------------------------------------------------------
struct GemmArgs {
    const __half *A, *B;
    const float* bias;
    float* C;
    __half* Ch;
    int M, N, K, lda, ldb, ldc;
    long aO, aI, bO, bI, cO, cI;
    int zdiv, batches, causal;
};

template<int EPI, int OUT>
static void launch_gemm(const GemmArgs& a)
{
    static bool attr_set = false;
    if (!attr_set) {
        cudaFuncSetAttribute(gemm_f16<EPI, OUT>,
                             cudaFuncAttributeMaxDynamicSharedMemorySize, GEMM_SMEM);
        attr_set = true;
    }
    dim3 grid(a.N / 128, a.M / 128, a.batches), block(256);
    gemm_f16<EPI, OUT><<<grid, block, GEMM_SMEM>>>(
        a.A, a.B, a.bias, a.C, a.Ch,
        a.M, a.N, a.K, a.lda, a.ldb, a.ldc,
        a.aO, a.aI, a.bO, a.bI, a.cO, a.cI, a.zdiv, a.causal);
}

extern "C" void kernel_launch(void* const* d_in, const int* in_sizes, int n_in,
                              void* d_out, int out_size)
{
    const int*   x        = (const int*)  d_in[0];
    const float* embed_W  = (const float*)d_in[1];
    const float* Wq       = (const float*)d_in[2];
    const float* Wk       = (const float*)d_in[3];
    const float* Wv       = (const float*)d_in[4];
    const float* Wu       = (const float*)d_in[5];
    const float* bu       = (const float*)d_in[6];
    const float* W1       = (const float*)d_in[7];
    const float* b1       = (const float*)d_in[8];
    const float* W2       = (const float*)d_in[9];
    const float* b2       = (const float*)d_in[10];
    const float* ln1_w    = (const float*)d_in[11];
    const float* ln1_b    = (const float*)d_in[12];
    const float* ln2_w    = (const float*)d_in[13];
    const float* ln2_b    = (const float*)d_in[14];
    const float* lnf_w    = (const float*)d_in[15];
    const float* lnf_b    = (const float*)d_in[16];
    const float* unembedW = (const float*)d_in[17];
    const float* unembedB = (const float*)d_in[18];
    float* out = (float*)d_out;

    float *h, *att;
    __half *hf, *wt, *qv, *vt, *as, *yf, *ff;
    cudaGetSymbolAddress((void**)&h,   g_h);
    cudaGetSymbolAddress((void**)&att, g_att);
    cudaGetSymbolAddress((void**)&hf,  g_hf);
    cudaGetSymbolAddress((void**)&wt,  g_wt);
    cudaGetSymbolAddress((void**)&qv,  g_qkv);
    cudaGetSymbolAddress((void**)&vt,  g_vt);
    cudaGetSymbolAddress((void**)&as,  g_as);
    cudaGetSymbolAddress((void**)&yf,  g_yf);
    cudaGetSymbolAddress((void**)&ff,  g_ff);

    embed_k<<<MTOK, 256>>>(x, embed_W, h, hf);

    const long atI = (long)SEQ * SEQ;          // 262144
    const long atO = (long)HEADS * atI;
    const long PS  = (long)MTOK * KD;          // split-K plane stride

    for (int i = 0; i < NBLK; i++) {
        const float* Wq_i = Wq + (size_t)i * KD * HK;
        const float* Wk_i = Wk + (size_t)i * KD * HK;
        const float* Wv_i = Wv + (size_t)i * KD * HK;
        const float* Wu_i = Wu + (size_t)i * HK * KD;
        const float* bu_i = bu + (size_t)i * KD;
        const float* W1_i = W1 + (size_t)i * KD * FF;
        const float* b1_i = b1 + (size_t)i * FF;
        const float* W2_i = W2 + (size_t)i * FF * KD;
        const float* b2_i = b2 + (size_t)i * KD;

        // fused QKV
        wconv3h<<<dim3(KD/32, HK/32, 3), dim3(32,8)>>>(Wq_i, Wk_i, Wv_i, wt);
        { GemmArgs a = {hf, wt, nullptr, nullptr, qv,
                        MTOK, QKVN, KD, KD, KD, QKVN, 0,0,0,0,0,0, 1, 1, 0};
          launch_gemm<0,2>(a); }

        // scores = Q @ K^T; skip upper-triangle tiles
        { GemmArgs a = {qv, qv + HK, nullptr, att, nullptr,
                        SEQ, SEQ, KD, QKVN, QKVN, SEQ,
                        (long)SEQ*QKVN, (long)KD, (long)SEQ*QKVN, (long)KD,
                        atO, atI, HEADS, NBH, 1};
          launch_gemm<0,0>(a); }

        softmax_k<<<dim3(SEQ, NBH), 256>>>(att, as);
        vconvh<<<dim3(16,16,NBH), dim3(32,8)>>>(qv, vt);

        // y = att @ V; truncate K per tile row
        { GemmArgs a = {as, vt, nullptr, nullptr, yf,
                        SEQ, KD, SEQ, SEQ, SEQ, HK,
                        atO, atI, atO, atI,
                        (long)SEQ*HK, (long)KD, HEADS, NBH, 2};
          launch_gemm<0,2>(a); }

        // proj: split-K=4 -> partial planes in att -> fused reduce+LN
        wconvh<<<dim3(HK/32, KD/32), dim3(32,8)>>>(Wu_i, wt, HK, KD);
        { GemmArgs a = {yf, wt, nullptr, att, nullptr,
                        MTOK, KD, 1024, HK, HK, KD,
                        1024, 0, 1024, 0, PS, 0, 1, 4, 0};
          launch_gemm<0,0>(a); }
        ln_red_k<<<MTOK, 256>>>(att, PS, bu_i, h, hf,
                                ln1_w + (size_t)i * KD, ln1_b + (size_t)i * KD);

        // ff = gelu(h @ W1 + b1) -> fp16
        wconvh<<<dim3(KD/32, FF/32), dim3(32,8)>>>(W1_i, wt, KD, FF);
        { GemmArgs a = {hf, wt, b1_i, nullptr, ff,
                        MTOK, FF, KD, KD, KD, FF, 0,0,0,0,0,0, 1, 1, 0};
          launch_gemm<2,2>(a); }

        // W2: split-K=4 -> partial planes -> fused reduce+LN
        wconvh<<<dim3(FF/32, KD/32), dim3(32,8)>>>(W2_i, wt, FF, KD);
        { GemmArgs a = {ff, wt, nullptr, att, nullptr,
                        MTOK, KD, 512, FF, FF, KD,
                        512, 0, 512, 0, PS, 0, 1, 4, 0};
          launch_gemm<0,0>(a); }
        ln_red_k<<<MTOK, 256>>>(att, PS, b2_i, h, hf,
                                ln2_w + (size_t)i * KD, ln2_b + (size_t)i * KD);
    }

    ln_k<<<MTOK, 256>>>(h, h, hf, lnf_w, lnf_b);

    // unembed
    wconvh<<<dim3(KD/32, VOCAB/32), dim3(32,8)>>>(unembedW, wt, KD, VOCAB);
    { GemmArgs a = {hf, wt, unembedB, out, nullptr,
                    MTOK, VOCAB, KD, KD, KD, VOCAB, 0,0,0,0,0,0, 1, 1, 0};
      launch_gemm<1,0>(a); }
}

// round 16
// speedup vs baseline: 1.0456x; 1.0456x over previous
#include <cuda_runtime.h>
#include <cuda_bf16.h>
#include <cuda_fp16.h>
#include <math.h>

// ---------------------------------------------------------------------------
// GPT forward. All-fp16 tensor-core GEMMs (fp32 accumulate), fp32 elementwise.
// B=4, T=512, K=512, H=8, NB=4, VOCAB=32000. M = B*T = 2048 tokens.
//
// R16: R14 GEMM core (32-k chunks) + 4-stage cp.async pipeline (wait_group 2,
// prefetch i+3) + fused split-K reduce+LayerNorm. fp16 single-pass GEMMs,
// fused QKV, causal skip/truncate, split-K skinny GEMMs.
// ---------------------------------------------------------------------------

#define BATCH 4
#define SEQ   512
#define KD    512
#define HEADS 8
#define NBLK  4
#define VOCAB 32000
#define MTOK  (BATCH*SEQ)        // 2048
#define HK    (HEADS*KD)         // 4096
#define QKVN  (3*HK)             // 12288
#define FF    (4*KD)             // 2048
#define NBH   (BATCH*HEADS)      // 32

// fp32 scratch
__device__ float g_h  [MTOK*KD];
__device__ float g_att[NBH*SEQ*SEQ];      // scores; reused as split-K partials
// fp16 scratch
__device__ __align__(256) __half g_hf  [MTOK*KD];
__device__ __align__(256) __half g_wt  [(size_t)VOCAB*KD];
__device__ __align__(256) __half g_qkv [(size_t)MTOK*QKVN];
__device__ __align__(256) __half g_vt  [MTOK*HK];
__device__ __align__(256) __half g_as  [NBH*SEQ*SEQ];
__device__ __align__(256) __half g_yf  [MTOK*HK];
__device__ __align__(256) __half g_ff  [MTOK*FF];

// ---------------------------------------------------------------------------
// helpers
// ---------------------------------------------------------------------------
__device__ __forceinline__ unsigned smem_u32(const void* p) {
    unsigned r;
    asm("{ .reg .u64 t; cvta.to.shared.u64 t, %1; cvt.u32.u64 %0, t; }"
        : "=r"(r) : "l"(p));
    return r;
}
__device__ __forceinline__ void cp16(unsigned dst, const void* src) {
    asm volatile("cp.async.cg.shared.global [%0], [%1], 16;" :: "r"(dst), "l"(src));
}
#define CP_COMMIT() asm volatile("cp.async.commit_group;" ::: "memory")
#define CP_WAIT2()  asm volatile("cp.async.wait_group 2;" ::: "memory")

__device__ __forceinline__ void ldsm4(unsigned addr, unsigned& r0, unsigned& r1,
                                      unsigned& r2, unsigned& r3) {
    asm volatile("ldmatrix.sync.aligned.m8n8.x4.shared.b16 {%0,%1,%2,%3}, [%4];"
                 : "=r"(r0), "=r"(r1), "=r"(r2), "=r"(r3) : "r"(addr));
}
__device__ __forceinline__ void ldsm2(unsigned addr, unsigned& r0, unsigned& r1) {
    asm volatile("ldmatrix.sync.aligned.m8n8.x2.shared.b16 {%0,%1}, [%2];"
                 : "=r"(r0), "=r"(r1) : "r"(addr));
}
__device__ __forceinline__ void mma_f16(float* c, const unsigned* a, const unsigned* b) {
    asm volatile(
        "mma.sync.aligned.m16n8k16.row.col.f32.f16.f16.f32 "
        "{%0,%1,%2,%3},{%4,%5,%6,%7},{%8,%9},{%0,%1,%2,%3};"
        : "+f"(c[0]), "+f"(c[1]), "+f"(c[2]), "+f"(c[3])
        : "r"(a[0]), "r"(a[1]), "r"(a[2]), "r"(a[3]), "r"(b[0]), "r"(b[1]));
}

// SMEM stage layout (uint32 units): [A 2048 | B 2048] (fp16, 32-k chunks)
// Tile row = 16 uint32 (32 fp16 along k), swizzle col' = c ^ ((row&6)<<1).
#define ST_U32 4096
#define A_OFF  0
#define B_OFF  2048
#define NSTAGE 4
#define GEMM_SMEM (NSTAGE*ST_U32*4)   // 65536 bytes

// ---------------------------------------------------------------------------
// Pipelined fp16 GEMM, 32-k chunks, 4-stage.  A: [M][K] fp16.  B: [N][K] fp16.
// C = A * B^T.  EPI: 0 none, 1 +bias, 2 gelu(x+bias).  OUT: 0 fp32, 2 fp16.
// causal: 0 none, 1 tile-skip (bx>by), 2 K-trunc to (by+1)*128.
// Batched / split-K via blockIdx.z. M%128==0, N%128==0, K%32==0.
// ---------------------------------------------------------------------------
template<int EPI, int OUT>
__global__ __launch_bounds__(256, 2)
void gemm_f16(const __half* __restrict__ A, const __half* __restrict__ B,
              const float* __restrict__ bias,
              float* __restrict__ C, __half* __restrict__ Ch,
              int M, int N, int K, int lda, int ldb, int ldc,
              long aO, long aI, long bO, long bI, long cO, long cI, int zdiv,
              int causal)
{
    extern __shared__ unsigned sm[];
    const unsigned base32 = smem_u32(sm);

    const int bx = blockIdx.x, by = blockIdx.y;
    if (causal == 1 && bx > by) return;
    if (causal == 2) K = min(K, (by + 1) * 128);

    const int z  = blockIdx.z;
    const int zb = z / zdiv, zh = z - zb * zdiv;
    const size_t aoff = (size_t)zb * aO + (size_t)zh * aI;
    const size_t boff = (size_t)zb * bO + (size_t)zh * bI;
    const size_t coff = (size_t)zb * cO + (size_t)zh * cI;
    A += aoff; B += boff;

    const int tid  = threadIdx.x;
    const int lane = tid & 31;
    const int warp = tid >> 5;
    const int g    = lane >> 2;
    const int tc   = lane & 3;
    const int wm   = (warp >> 2) * 64;
    const int wn   = (warp & 3) * 32;

    const int crow = tid >> 1;
    const int cj   = (tid & 1) * 2;
    const __half* pA = A + (size_t)(by * 128 + crow) * lda + cj * 8;
    const __half* pB = B + (size_t)(bx * 128 + crow) * ldb + cj * 8;
    const int csw = (crow & 6) << 1;
    const int cs0 = crow * 16 + ((4 * cj)     ^ csw);
    const int cs1 = crow * 16 + ((4 * cj + 4) ^ csw);

    int idxA[4][2], idxB[4][2];
    {
        const int rowA = wm + (lane & 15);
        const int cgA0 = (lane >> 4) << 2;
        const int rowB = wn + (lane & 7);
        const int cgB0 = ((lane >> 3) & 1) << 2;
        #pragma unroll
        for (int mf = 0; mf < 4; mf++) {
            const int r = rowA + mf * 16;
            idxA[mf][0] = r * 16 + ((cgA0)     ^ ((r & 6) << 1));
            idxA[mf][1] = r * 16 + ((cgA0 + 8) ^ ((r & 6) << 1));
        }
        #pragma unroll
        for (int nf = 0; nf < 4; nf++) {
            const int r = rowB + nf * 8;
            idxB[nf][0] = r * 16 + ((cgB0)     ^ ((r & 6) << 1));
            idxB[nf][1] = r * 16 + ((cgB0 + 8) ^ ((r & 6) << 1));
        }
    }

    float acc[4][4][4];
    #pragma unroll
    for (int i = 0; i < 4; i++)
        #pragma unroll
        for (int j = 0; j < 4; j++)
            #pragma unroll
            for (int r = 0; r < 4; r++) acc[i][j][r] = 0.f;

    auto ISSUE = [&](int buf, int k0) {
        const unsigned sb = base32 + buf * (ST_U32 * 4);
        cp16(sb + (A_OFF + cs0) * 4, pA + k0);
        cp16(sb + (A_OFF + cs1) * 4, pA + k0 + 8);
        cp16(sb + (B_OFF + cs0) * 4, pB + k0);
        cp16(sb + (B_OFF + cs1) * 4, pB + k0 + 8);
    };

    const int nc = K >> 5;

    ISSUE(0, 0);  CP_COMMIT();
    if (nc > 1) ISSUE(1, 32);
    CP_COMMIT();
    if (nc > 2) ISSUE(2, 64);
    CP_COMMIT();

    for (int i = 0; i < nc; i++) {
        CP_WAIT2();            // chunk i resident (2 younger groups may be in flight)
        __syncthreads();       // all warps finished computing chunk i-1

        // buffer (i+3)%4 == (i-1)%4 is free after the barrier
        if (i + 3 < nc) ISSUE((i + 3) % NSTAGE, (i + 3) * 32);
        CP_COMMIT();

        const unsigned stb = base32 + (i % NSTAGE) * (ST_U32 * 4);
        #pragma unroll
        for (int kpb = 0; kpb < 2; kpb++) {
            unsigned Bf[4][2];
            #pragma unroll
            for (int nf = 0; nf < 4; nf++)
                ldsm2(stb + (B_OFF + idxB[nf][kpb]) * 4, Bf[nf][0], Bf[nf][1]);
            #pragma unroll
            for (int mf = 0; mf < 4; mf++) {
                unsigned Aa[4];
                ldsm4(stb + (A_OFF + idxA[mf][kpb]) * 4, Aa[0], Aa[1], Aa[2], Aa[3]);
                #pragma unroll
                for (int nf = 0; nf < 4; nf++)
                    mma_f16(acc[mf][nf], Aa, Bf[nf]);
            }
        }
    }

    // ---- epilogue ----
    #pragma unroll
    for (int mf = 0; mf < 4; mf++) {
        const int r0 = by * 128 + wm + mf * 16 + g;
        #pragma unroll
        for (int nf = 0; nf < 4; nf++) {
            const int col = bx * 128 + wn + nf * 8 + tc * 2;
            float c0 = acc[mf][nf][0], c1 = acc[mf][nf][1];
            float c2 = acc[mf][nf][2], c3 = acc[mf][nf][3];
            if (EPI >= 1) {
                const float b0v = bias[col], b1v = bias[col + 1];
                c0 += b0v; c1 += b1v; c2 += b0v; c3 += b1v;
            }
            if (EPI == 2) {
                c0 = 0.5f * c0 * (1.0f + erff(c0 * 0.7071067811865475f));
                c1 = 0.5f * c1 * (1.0f + erff(c1 * 0.7071067811865475f));
                c2 = 0.5f * c2 * (1.0f + erff(c2 * 0.7071067811865475f));
                c3 = 0.5f * c3 * (1.0f + erff(c3 * 0.7071067811865475f));
            }
            if (OUT == 0) {
                *(float2*)&C[coff + (size_t)r0 * ldc + col]       = make_float2(c0, c1);
                *(float2*)&C[coff + (size_t)(r0 + 8) * ldc + col] = make_float2(c2, c3);
            } else {
                *(__half2*)&Ch[coff + (size_t)r0 * ldc + col]       = __floats2half2_rn(c0, c1);
                *(__half2*)&Ch[coff + (size_t)(r0 + 8) * ldc + col] = __floats2half2_rn(c2, c3);
            }
        }
    }
}

// ---------------------------------------------------------------------------
// Fused split-K reduce + residual + LayerNorm.
// x = sum_{s<4} P[s*PS + i] + bias[col] + h[i]; h = LN(x)*w + b; hf = fp16(h).
// ---------------------------------------------------------------------------
__global__ void ln_red_k(const float* __restrict__ P, long PS,
                         const float* __restrict__ bias,
                         float* __restrict__ h, __half* __restrict__ hf,
                         const float* __restrict__ w, const float* __restrict__ b)
{
    const int token = blockIdx.x;
    const size_t base = (size_t)token * KD;
    const int tid = threadIdx.x;
    float x0 = bias[tid]       + h[base + tid];
    float x1 = bias[tid + 256] + h[base + tid + 256];
    #pragma unroll
    for (int s = 0; s < 4; s++) {
        x0 += P[(size_t)s * PS + base + tid];
        x1 += P[(size_t)s * PS + base + tid + 256];
    }
    __shared__ float s1[256], s2[256];
    s1[tid] = x0 + x1;
    s2[tid] = x0 * x0 + x1 * x1;
    __syncthreads();
    for (int o = 128; o; o >>= 1) {
        if (tid < o) { s1[tid] += s1[tid + o]; s2[tid] += s2[tid + o]; }
        __syncthreads();
    }
    const float mean = s1[0] * (1.f / KD);
    const float var  = s2[0] * (1.f / KD) - mean * mean;
    const float r = rsqrtf(var + 1e-5f);
    const float y0 = (x0 - mean) * r * w[tid]       + b[tid];
    const float y1 = (x1 - mean) * r * w[tid + 256] + b[tid + 256];
    h[base + tid]        = y0;
    h[base + tid + 256]  = y1;
    hf[base + tid]       = __float2half(y0);
    hf[base + tid + 256] = __float2half(y1);
}

// Plain LayerNorm (no residual) for the final LN.
__global__ void ln_k(const float* __restrict__ src, float* __restrict__ h,
                     __half* __restrict__ hf,
                     const float* __restrict__ w, const float* __restrict__ b)
{
    const int token = blockIdx.x;
    const size_t base = (size_t)token * KD;
    const int tid = threadIdx.x;
    const float x0 = src[base + tid];
    const float x1 = src[base + tid + 256];
    __shared__ float s1[256], s2[256];
    s1[tid] = x0 + x1;
    s2[tid] = x0 * x0 + x1 * x1;
    __syncthreads();
    for (int o = 128; o; o >>= 1) {
        if (tid < o) { s1[tid] += s1[tid + o]; s2[tid] += s2[tid + o]; }
        __syncthreads();
    }
    const float mean = s1[0] * (1.f / KD);
    const float var  = s2[0] * (1.f / KD) - mean * mean;
    const float r = rsqrtf(var + 1e-5f);
    const float y0 = (x0 - mean) * r * w[tid]       + b[tid];
    const float y1 = (x1 - mean) * r * w[tid + 256] + b[tid + 256];
    h[base + tid]        = y0;
    h[base + tid + 256]  = y1;
    hf[base + tid]       = __float2half(y0);
    hf[base + tid + 256] = __float2half(y1);
}

// ---------------------------------------------------------------------------
// Weight transpose, fp16: src fp32 [K][N] -> dst fp16 [N][K].
// ---------------------------------------------------------------------------
__global__ void wconvh(const float* __restrict__ src, __half* __restrict__ dh,
                       int K, int N)
{
    __shared__ float t[32][33];
    const int k0 = blockIdx.x * 32, n0 = blockIdx.y * 32;
    const int tx = threadIdx.x, ty = threadIdx.y;
    #pragma unroll
    for (int r = 0; r < 4; r++)
        t[ty + r * 8][tx] = src[(size_t)(k0 + ty + r * 8) * N + n0 + tx];
    __syncthreads();
    #pragma unroll
    for (int r = 0; r < 4; r++)
        dh[(size_t)(n0 + ty + r * 8) * K + k0 + tx] = __float2half(t[tx][ty + r * 8]);
}

// Fused Wq/Wk/Wv transpose -> fp16 [QKVN][KD]. grid z picks src.
__global__ void wconv3h(const float* __restrict__ s0, const float* __restrict__ s1,
                        const float* __restrict__ s2, __half* __restrict__ dh)
{
    __shared__ float t[32][33];
    const float* src = (blockIdx.z == 0) ? s0 : (blockIdx.z == 1 ? s1 : s2);
    const int k0 = blockIdx.x * 32, n0 = blockIdx.y * 32;
    const int tx = threadIdx.x, ty = threadIdx.y;
    #pragma unroll
    for (int r = 0; r < 4; r++)
        t[ty + r * 8][tx] = src[(size_t)(k0 + ty + r * 8) * HK + n0 + tx];
    __syncthreads();
    const size_t rowoff = (size_t)blockIdx.z * HK;
    #pragma unroll
    for (int r = 0; r < 4; r++)
        dh[(rowoff + n0 + ty + r * 8) * KD + k0 + tx] = __float2half(t[tx][ty + r * 8]);
}

// ---------------------------------------------------------------------------
// V transpose per head from fp16 QKV buffer -> fp16 [(b*8+h)*512+d][t].
// ---------------------------------------------------------------------------
__global__ void vconvh(const __half* __restrict__ qv, __half* __restrict__ dh)
{
    __shared__ __half t[32][33];
    const int z = blockIdx.z, b = z >> 3, h = z & 7;
    const int t0 = blockIdx.x * 32, d0 = blockIdx.y * 32;
    const int tx = threadIdx.x, ty = threadIdx.y;
    #pragma unroll
    for (int r = 0; r < 4; r++) {
        const size_t si = (size_t)(b * SEQ + t0 + ty + r * 8) * QKVN
                        + 2 * HK + h * KD + d0 + tx;
        t[ty + r * 8][tx] = qv[si];
    }
    __syncthreads();
    #pragma unroll
    for (int r = 0; r < 4; r++) {
        const size_t o = ((size_t)z * KD + d0 + ty + r * 8) * SEQ + t0 + tx;
        dh[o] = t[tx][ty + r * 8];
    }
}

// ---------------------------------------------------------------------------
// Embedding + positional encoding.
// ---------------------------------------------------------------------------
__global__ void embed_k(const int* __restrict__ x, const float* __restrict__ W,
                        float* __restrict__ h, __half* __restrict__ hf)
{
    const int token = blockIdx.x;
    const int t  = token & (SEQ - 1);
    const int id = x[token];
    const int tid = threadIdx.x;
    #pragma unroll
    for (int u = 0; u < 2; u++) {
        const int c = tid + u * 256;
        const int j = c >> 1;
        const float ang = (float)t * expf(-(float)j * 0.07195578415606394f);
        const float p = (c & 1) ? cosf(ang) : sinf(ang);
        const float val = W[(size_t)id * KD + c] + p;
        const size_t o = (size_t)token * KD + c;
        h[o] = val;
        hf[o] = __float2half(val);
    }
}

// ---------------------------------------------------------------------------
// Causal softmax (scale folded), writes fp16 att.
// ---------------------------------------------------------------------------
__global__ void softmax_k(const float* __restrict__ att, __half* __restrict__ oh)
{
    const int q  = blockIdx.x;
    const int bh = blockIdx.y;
    const size_t base = ((size_t)bh * SEQ + q) * SEQ;
    const int tid = threadIdx.x;
    const float scale = 0.04419417382415922f;  // 1/sqrt(512)
    __shared__ float red[256];

    const float s0 = (tid       <= q) ? att[base + tid]       * scale : -3.4e38f;
    const float s1 = (tid + 256 <= q) ? att[base + tid + 256] * scale : -3.4e38f;
    red[tid] = fmaxf(s0, s1);
    __syncthreads();
    for (int o = 128; o; o >>= 1) {
        if (tid < o) red[tid] = fmaxf(red[tid], red[tid + o]);
        __syncthreads();
    }
    const float m = red[0];
    __syncthreads();
    const float v0 = (tid       <= q) ? expf(s0 - m) : 0.f;
    const float v1 = (tid + 256 <= q) ? expf(s1 - m) : 0.f;
    red[tid] = v0 + v1;
    __syncthreads();
    for (int o = 128; o; o >>= 1) {
        if (tid < o) red[tid] += red[tid + o];
        __syncthreads();
    }
    const float inv = 1.0f / red[0];
    oh[base + tid]       = __float2half(v0 * inv);
    oh[base + tid + 256] = __float2half(v1 * inv);
}

// ---------------------------------------------------------------------------
// Host-side launcher
// ---------------------------------------------------------------------------
struct GemmArgs {
    const __half *A, *B;
    const float* bias;
    float* C;
    __half* Ch;
    int M, N, K, lda, ldb, ldc;
    long aO, aI, bO, bI, cO, cI;
    int zdiv, batches, causal;
};

template<int EPI, int OUT>
static void launch_gemm(const GemmArgs& a)
{
    static bool attr_set = false;
    if (!attr_set) {
        cudaFuncSetAttribute(gemm_f16<EPI, OUT>,
                             cudaFuncAttributeMaxDynamicSharedMemorySize, GEMM_SMEM);
        attr_set = true;
    }
    dim3 grid(a.N / 128, a.M / 128, a.batches), block(256);
    gemm_f16<EPI, OUT><<<grid, block, GEMM_SMEM>>>(
        a.A, a.B, a.bias, a.C, a.Ch,
        a.M, a.N, a.K, a.lda, a.ldb, a.ldc,
        a.aO, a.aI, a.bO, a.bI, a.cO, a.cI, a.zdiv, a.causal);
}

extern "C" void kernel_launch(void* const* d_in, const int* in_sizes, int n_in,
                              void* d_out, int out_size)
{
    const int*   x        = (const int*)  d_in[0];
    const float* embed_W  = (const float*)d_in[1];
    const float* Wq       = (const float*)d_in[2];
    const float* Wk       = (const float*)d_in[3];
    const float* Wv       = (const float*)d_in[4];
    const float* Wu       = (const float*)d_in[5];
    const float* bu       = (const float*)d_in[6];
    const float* W1       = (const float*)d_in[7];
    const float* b1       = (const float*)d_in[8];
    const float* W2       = (const float*)d_in[9];
    const float* b2       = (const float*)d_in[10];
    const float* ln1_w    = (const float*)d_in[11];
    const float* ln1_b    = (const float*)d_in[12];
    const float* ln2_w    = (const float*)d_in[13];
    const float* ln2_b    = (const float*)d_in[14];
    const float* lnf_w    = (const float*)d_in[15];
    const float* lnf_b    = (const float*)d_in[16];
    const float* unembedW = (const float*)d_in[17];
    const float* unembedB = (const float*)d_in[18];
    float* out = (float*)d_out;

    float *h, *att;
    __half *hf, *wt, *qv, *vt, *as, *yf, *ff;
    cudaGetSymbolAddress((void**)&h,   g_h);
    cudaGetSymbolAddress((void**)&att, g_att);
    cudaGetSymbolAddress((void**)&hf,  g_hf);
    cudaGetSymbolAddress((void**)&wt,  g_wt);
    cudaGetSymbolAddress((void**)&qv,  g_qkv);
    cudaGetSymbolAddress((void**)&vt,  g_vt);
    cudaGetSymbolAddress((void**)&as,  g_as);
    cudaGetSymbolAddress((void**)&yf,  g_yf);
    cudaGetSymbolAddress((void**)&ff,  g_ff);

    embed_k<<<MTOK, 256>>>(x, embed_W, h, hf);

    const long atI = (long)SEQ * SEQ;          // 262144
    const long atO = (long)HEADS * atI;
    const long PS  = (long)MTOK * KD;          // split-K plane stride

    for (int i = 0; i < NBLK; i++) {
        const float* Wq_i = Wq + (size_t)i * KD * HK;
        const float* Wk_i = Wk + (size_t)i * KD * HK;
        const float* Wv_i = Wv + (size_t)i * KD * HK;
        const float* Wu_i = Wu + (size_t)i * HK * KD;
        const float* bu_i = bu + (size_t)i * KD;
        const float* W1_i = W1 + (size_t)i * KD * FF;
        const float* b1_i = b1 + (size_t)i * FF;
        const float* W2_i = W2 + (size_t)i * FF * KD;
        const float* b2_i = b2 + (size_t)i * KD;

        // fused QKV
        wconv3h<<<dim3(KD/32, HK/32, 3), dim3(32,8)>>>(Wq_i, Wk_i, Wv_i, wt);
        { GemmArgs a = {hf, wt, nullptr, nullptr, qv,
                        MTOK, QKVN, KD, KD, KD, QKVN, 0,0,0,0,0,0, 1, 1, 0};
          launch_gemm<0,2>(a); }

        // scores = Q @ K^T; skip upper-triangle tiles
        { GemmArgs a = {qv, qv + HK, nullptr, att, nullptr,
                        SEQ, SEQ, KD, QKVN, QKVN, SEQ,
                        (long)SEQ*QKVN, (long)KD, (long)SEQ*QKVN, (long)KD,
                        atO, atI, HEADS, NBH, 1};
          launch_gemm<0,0>(a); }

        softmax_k<<<dim3(SEQ, NBH), 256>>>(att, as);
        vconvh<<<dim3(16,16,NBH), dim3(32,8)>>>(qv, vt);

        // y = att @ V; truncate K per tile row
        { GemmArgs a = {as, vt, nullptr, nullptr, yf,
                        SEQ, KD, SEQ, SEQ, SEQ, HK,
                        atO, atI, atO, atI,
                        (long)SEQ*HK, (long)KD, HEADS, NBH, 2};
          launch_gemm<0,2>(a); }

        // proj: split-K=4 -> partial planes in att -> fused reduce+LN
        wconvh<<<dim3(HK/32, KD/32), dim3(32,8)>>>(Wu_i, wt, HK, KD);
        { GemmArgs a = {yf, wt, nullptr, att, nullptr,
                        MTOK, KD, 1024, HK, HK, KD,
                        1024, 0, 1024, 0, PS, 0, 1, 4, 0};
          launch_gemm<0,0>(a); }
        ln_red_k<<<MTOK, 256>>>(att, PS, bu_i, h, hf,
                                ln1_w + (size_t)i * KD, ln1_b + (size_t)i * KD);

        // ff = gelu(h @ W1 + b1) -> fp16
        wconvh<<<dim3(KD/32, FF/32), dim3(32,8)>>>(W1_i, wt, KD, FF);
        { GemmArgs a = {hf, wt, b1_i, nullptr, ff,
                        MTOK, FF, KD, KD, KD, FF, 0,0,0,0,0,0, 1, 1, 0};
          launch_gemm<2,2>(a); }

        // W2: split-K=4 -> partial planes -> fused reduce+LN
        wconvh<<<dim3(FF/32, KD/32), dim3(32,8)>>>(W2_i, wt, FF, KD);
        { GemmArgs a = {ff, wt, nullptr, att, nullptr,
                        MTOK, KD, 512, FF, FF, KD,
                        512, 0, 512, 0, PS, 0, 1, 4, 0};
          launch_gemm<0,0>(a); }
        ln_red_k<<<MTOK, 256>>>(att, PS, b2_i, h, hf,
                                ln2_w + (size_t)i * KD, ln2_b + (size_t)i * KD);
    }

    ln_k<<<MTOK, 256>>>(h, h, hf, lnf_w, lnf_b);

    // unembed
    wconvh<<<dim3(KD/32, VOCAB/32), dim3(32,8)>>>(unembedW, wt, KD, VOCAB);
    { GemmArgs a = {hf, wt, unembedB, out, nullptr,
                    MTOK, VOCAB, KD, KD, KD, VOCAB, 0,0,0,0,0,0, 1, 1, 0};
      launch_gemm<1,0>(a); }
}

// round 17
// speedup vs baseline: 1.0731x; 1.0264x over previous
#include <cuda_runtime.h>
#include <cuda_bf16.h>
#include <cuda_fp16.h>
#include <math.h>

// ---------------------------------------------------------------------------
// GPT forward. All-fp16 tensor-core GEMMs (fp32 accumulate), fp32 elementwise.
// B=4, T=512, K=512, H=8, NB=4, VOCAB=32000. M = B*T = 2048 tokens.
//
// R17: R14 GEMM core verbatim (32-k chunks, 3-stage cp.async wait_group 1,
// prefetch i+2 — the measured-best schedule) + fused split-K reduce+LayerNorm
// (ln_red_k). fp16 single-pass GEMMs, fused QKV, causal skip/truncate,
// split-K skinny GEMMs.
// ---------------------------------------------------------------------------

#define BATCH 4
#define SEQ   512
#define KD    512
#define HEADS 8
#define NBLK  4
#define VOCAB 32000
#define MTOK  (BATCH*SEQ)        // 2048
#define HK    (HEADS*KD)         // 4096
#define QKVN  (3*HK)             // 12288
#define FF    (4*KD)             // 2048
#define NBH   (BATCH*HEADS)      // 32

// fp32 scratch
__device__ float g_h  [MTOK*KD];
__device__ float g_att[NBH*SEQ*SEQ];      // scores; reused as split-K partials
// fp16 scratch
__device__ __align__(256) __half g_hf  [MTOK*KD];
__device__ __align__(256) __half g_wt  [(size_t)VOCAB*KD];
__device__ __align__(256) __half g_qkv [(size_t)MTOK*QKVN];
__device__ __align__(256) __half g_vt  [MTOK*HK];
__device__ __align__(256) __half g_as  [NBH*SEQ*SEQ];
__device__ __align__(256) __half g_yf  [MTOK*HK];
__device__ __align__(256) __half g_ff  [MTOK*FF];

// ---------------------------------------------------------------------------
// helpers
// ---------------------------------------------------------------------------
__device__ __forceinline__ unsigned smem_u32(const void* p) {
    unsigned r;
    asm("{ .reg .u64 t; cvta.to.shared.u64 t, %1; cvt.u32.u64 %0, t; }"
        : "=r"(r) : "l"(p));
    return r;
}
__device__ __forceinline__ void cp16(unsigned dst, const void* src) {
    asm volatile("cp.async.cg.shared.global [%0], [%1], 16;" :: "r"(dst), "l"(src));
}
#define CP_COMMIT() asm volatile("cp.async.commit_group;" ::: "memory")
#define CP_WAIT1()  asm volatile("cp.async.wait_group 1;" ::: "memory")

__device__ __forceinline__ void ldsm4(unsigned addr, unsigned& r0, unsigned& r1,
                                      unsigned& r2, unsigned& r3) {
    asm volatile("ldmatrix.sync.aligned.m8n8.x4.shared.b16 {%0,%1,%2,%3}, [%4];"
                 : "=r"(r0), "=r"(r1), "=r"(r2), "=r"(r3) : "r"(addr));
}
__device__ __forceinline__ void ldsm2(unsigned addr, unsigned& r0, unsigned& r1) {
    asm volatile("ldmatrix.sync.aligned.m8n8.x2.shared.b16 {%0,%1}, [%2];"
                 : "=r"(r0), "=r"(r1) : "r"(addr));
}
__device__ __forceinline__ void mma_f16(float* c, const unsigned* a, const unsigned* b) {
    asm volatile(
        "mma.sync.aligned.m16n8k16.row.col.f32.f16.f16.f32 "
        "{%0,%1,%2,%3},{%4,%5,%6,%7},{%8,%9},{%0,%1,%2,%3};"
        : "+f"(c[0]), "+f"(c[1]), "+f"(c[2]), "+f"(c[3])
        : "r"(a[0]), "r"(a[1]), "r"(a[2]), "r"(a[3]), "r"(b[0]), "r"(b[1]));
}

// SMEM stage layout (uint32 units): [A 2048 | B 2048] (fp16, 32-k chunks)
// Tile row = 16 uint32 (32 fp16 along k), swizzle col' = c ^ ((row&6)<<1).
#define ST_U32 4096
#define A_OFF  0
#define B_OFF  2048
#define NSTAGE 3
#define GEMM_SMEM (NSTAGE*ST_U32*4)   // 49152 bytes

// ---------------------------------------------------------------------------
// Pipelined fp16 GEMM, 32-k chunks, 3-stage (R14 schedule).
// A: [M][K] fp16.  B: [N][K] fp16.  C = A * B^T.
// EPI: 0 none, 1 +bias, 2 gelu(x+bias).  OUT: 0 fp32, 2 fp16.
// causal: 0 none, 1 tile-skip (bx>by), 2 K-trunc to (by+1)*128.
// Batched / split-K via blockIdx.z. M%128==0, N%128==0, K%32==0.
// ---------------------------------------------------------------------------
template<int EPI, int OUT>
__global__ __launch_bounds__(256, 2)
void gemm_f16(const __half* __restrict__ A, const __half* __restrict__ B,
              const float* __restrict__ bias,
              float* __restrict__ C, __half* __restrict__ Ch,
              int M, int N, int K, int lda, int ldb, int ldc,
              long aO, long aI, long bO, long bI, long cO, long cI, int zdiv,
              int causal)
{
    extern __shared__ unsigned sm[];
    const unsigned base32 = smem_u32(sm);

    const int bx = blockIdx.x, by = blockIdx.y;
    if (causal == 1 && bx > by) return;
    if (causal == 2) K = min(K, (by + 1) * 128);

    const int z  = blockIdx.z;
    const int zb = z / zdiv, zh = z - zb * zdiv;
    const size_t aoff = (size_t)zb * aO + (size_t)zh * aI;
    const size_t boff = (size_t)zb * bO + (size_t)zh * bI;
    const size_t coff = (size_t)zb * cO + (size_t)zh * cI;
    A += aoff; B += boff;

    const int tid  = threadIdx.x;
    const int lane = tid & 31;
    const int warp = tid >> 5;
    const int g    = lane >> 2;
    const int tc   = lane & 3;
    const int wm   = (warp >> 2) * 64;
    const int wn   = (warp & 3) * 32;

    const int crow = tid >> 1;
    const int cj   = (tid & 1) * 2;
    const __half* pA = A + (size_t)(by * 128 + crow) * lda + cj * 8;
    const __half* pB = B + (size_t)(bx * 128 + crow) * ldb + cj * 8;
    const int csw = (crow & 6) << 1;
    const int cs0 = crow * 16 + ((4 * cj)     ^ csw);
    const int cs1 = crow * 16 + ((4 * cj + 4) ^ csw);

    int idxA[4][2], idxB[4][2];
    {
        const int rowA = wm + (lane & 15);
        const int cgA0 = (lane >> 4) << 2;
        const int rowB = wn + (lane & 7);
        const int cgB0 = ((lane >> 3) & 1) << 2;
        #pragma unroll
        for (int mf = 0; mf < 4; mf++) {
            const int r = rowA + mf * 16;
            idxA[mf][0] = r * 16 + ((cgA0)     ^ ((r & 6) << 1));
            idxA[mf][1] = r * 16 + ((cgA0 + 8) ^ ((r & 6) << 1));
        }
        #pragma unroll
        for (int nf = 0; nf < 4; nf++) {
            const int r = rowB + nf * 8;
            idxB[nf][0] = r * 16 + ((cgB0)     ^ ((r & 6) << 1));
            idxB[nf][1] = r * 16 + ((cgB0 + 8) ^ ((r & 6) << 1));
        }
    }

    float acc[4][4][4];
    #pragma unroll
    for (int i = 0; i < 4; i++)
        #pragma unroll
        for (int j = 0; j < 4; j++)
            #pragma unroll
            for (int r = 0; r < 4; r++) acc[i][j][r] = 0.f;

    auto ISSUE = [&](int buf, int k0) {
        const unsigned sb = base32 + buf * (ST_U32 * 4);
        cp16(sb + (A_OFF + cs0) * 4, pA + k0);
        cp16(sb + (A_OFF + cs1) * 4, pA + k0 + 8);
        cp16(sb + (B_OFF + cs0) * 4, pB + k0);
        cp16(sb + (B_OFF + cs1) * 4, pB + k0 + 8);
    };

    const int nc = K >> 5;

    ISSUE(0, 0);  CP_COMMIT();
    if (nc > 1) ISSUE(1, 32);
    CP_COMMIT();

    for (int i = 0; i < nc; i++) {
        CP_WAIT1();
        __syncthreads();

        if (i + 2 < nc) ISSUE((i + 2) % NSTAGE, (i + 2) * 32);
        CP_COMMIT();

        const unsigned stb = base32 + (i % NSTAGE) * (ST_U32 * 4);
        #pragma unroll
        for (int kpb = 0; kpb < 2; kpb++) {
            unsigned Bf[4][2];
            #pragma unroll
            for (int nf = 0; nf < 4; nf++)
                ldsm2(stb + (B_OFF + idxB[nf][kpb]) * 4, Bf[nf][0], Bf[nf][1]);
            #pragma unroll
            for (int mf = 0; mf < 4; mf++) {
                unsigned Aa[4];
                ldsm4(stb + (A_OFF + idxA[mf][kpb]) * 4, Aa[0], Aa[1], Aa[2], Aa[3]);
                #pragma unroll
                for (int nf = 0; nf < 4; nf++)
                    mma_f16(acc[mf][nf], Aa, Bf[nf]);
            }
        }
    }

    // ---- epilogue ----
    #pragma unroll
    for (int mf = 0; mf < 4; mf++) {
        const int r0 = by * 128 + wm + mf * 16 + g;
        #pragma unroll
        for (int nf = 0; nf < 4; nf++) {
            const int col = bx * 128 + wn + nf * 8 + tc * 2;
            float c0 = acc[mf][nf][0], c1 = acc[mf][nf][1];
            float c2 = acc[mf][nf][2], c3 = acc[mf][nf][3];
            if (EPI >= 1) {
                const float b0v = bias[col], b1v = bias[col + 1];
                c0 += b0v; c1 += b1v; c2 += b0v; c3 += b1v;
            }
            if (EPI == 2) {
                c0 = 0.5f * c0 * (1.0f + erff(c0 * 0.7071067811865475f));
                c1 = 0.5f * c1 * (1.0f + erff(c1 * 0.7071067811865475f));
                c2 = 0.5f * c2 * (1.0f + erff(c2 * 0.7071067811865475f));
                c3 = 0.5f * c3 * (1.0f + erff(c3 * 0.7071067811865475f));
            }
            if (OUT == 0) {
                *(float2*)&C[coff + (size_t)r0 * ldc + col]       = make_float2(c0, c1);
                *(float2*)&C[coff + (size_t)(r0 + 8) * ldc + col] = make_float2(c2, c3);
            } else {
                *(__half2*)&Ch[coff + (size_t)r0 * ldc + col]       = __floats2half2_rn(c0, c1);
                *(__half2*)&Ch[coff + (size_t)(r0 + 8) * ldc + col] = __floats2half2_rn(c2, c3);
            }
        }
    }
}

// ---------------------------------------------------------------------------
// Fused split-K reduce + residual + LayerNorm.
// x = sum_{s<4} P[s*PS + i] + bias[col] + h[i]; h = LN(x)*w + b; hf = fp16(h).
// ---------------------------------------------------------------------------
__global__ void ln_red_k(const float* __restrict__ P, long PS,
                         const float* __restrict__ bias,
                         float* __restrict__ h, __half* __restrict__ hf,
                         const float* __restrict__ w, const float* __restrict__ b)
{
    const int token = blockIdx.x;
    const size_t base = (size_t)token * KD;
    const int tid = threadIdx.x;
    float x0 = bias[tid]       + h[base + tid];
    float x1 = bias[tid + 256] + h[base + tid + 256];
    #pragma unroll
    for (int s = 0; s < 4; s++) {
        x0 += P[(size_t)s * PS + base + tid];
        x1 += P[(size_t)s * PS + base + tid + 256];
    }
    __shared__ float s1[256], s2[256];
    s1[tid] = x0 + x1;
    s2[tid] = x0 * x0 + x1 * x1;
    __syncthreads();
    for (int o = 128; o; o >>= 1) {
        if (tid < o) { s1[tid] += s1[tid + o]; s2[tid] += s2[tid + o]; }
        __syncthreads();
    }
    const float mean = s1[0] * (1.f / KD);
    const float var  = s2[0] * (1.f / KD) - mean * mean;
    const float r = rsqrtf(var + 1e-5f);
    const float y0 = (x0 - mean) * r * w[tid]       + b[tid];
    const float y1 = (x1 - mean) * r * w[tid + 256] + b[tid + 256];
    h[base + tid]        = y0;
    h[base + tid + 256]  = y1;
    hf[base + tid]       = __float2half(y0);
    hf[base + tid + 256] = __float2half(y1);
}

// Plain LayerNorm (no residual) for the final LN.
__global__ void ln_k(const float* __restrict__ src, float* __restrict__ h,
                     __half* __restrict__ hf,
                     const float* __restrict__ w, const float* __restrict__ b)
{
    const int token = blockIdx.x;
    const size_t base = (size_t)token * KD;
    const int tid = threadIdx.x;
    const float x0 = src[base + tid];
    const float x1 = src[base + tid + 256];
    __shared__ float s1[256], s2[256];
    s1[tid] = x0 + x1;
    s2[tid] = x0 * x0 + x1 * x1;
    __syncthreads();
    for (int o = 128; o; o >>= 1) {
        if (tid < o) { s1[tid] += s1[tid + o]; s2[tid] += s2[tid + o]; }
        __syncthreads();
    }
    const float mean = s1[0] * (1.f / KD);
    const float var  = s2[0] * (1.f / KD) - mean * mean;
    const float r = rsqrtf(var + 1e-5f);
    const float y0 = (x0 - mean) * r * w[tid]       + b[tid];
    const float y1 = (x1 - mean) * r * w[tid + 256] + b[tid + 256];
    h[base + tid]        = y0;
    h[base + tid + 256]  = y1;
    hf[base + tid]       = __float2half(y0);
    hf[base + tid + 256] = __float2half(y1);
}

// ---------------------------------------------------------------------------
// Weight transpose, fp16: src fp32 [K][N] -> dst fp16 [N][K].
// ---------------------------------------------------------------------------
__global__ void wconvh(const float* __restrict__ src, __half* __restrict__ dh,
                       int K, int N)
{
    __shared__ float t[32][33];
    const int k0 = blockIdx.x * 32, n0 = blockIdx.y * 32;
    const int tx = threadIdx.x, ty = threadIdx.y;
    #pragma unroll
    for (int r = 0; r < 4; r++)
        t[ty + r * 8][tx] = src[(size_t)(k0 + ty + r * 8) * N + n0 + tx];
    __syncthreads();
    #pragma unroll
    for (int r = 0; r < 4; r++)
        dh[(size_t)(n0 + ty + r * 8) * K + k0 + tx] = __float2half(t[tx][ty + r * 8]);
}

// Fused Wq/Wk/Wv transpose -> fp16 [QKVN][KD]. grid z picks src.
__global__ void wconv3h(const float* __restrict__ s0, const float* __restrict__ s1,
                        const float* __restrict__ s2, __half* __restrict__ dh)
{
    __shared__ float t[32][33];
    const float* src = (blockIdx.z == 0) ? s0 : (blockIdx.z == 1 ? s1 : s2);
    const int k0 = blockIdx.x * 32, n0 = blockIdx.y * 32;
    const int tx = threadIdx.x, ty = threadIdx.y;
    #pragma unroll
    for (int r = 0; r < 4; r++)
        t[ty + r * 8][tx] = src[(size_t)(k0 + ty + r * 8) * HK + n0 + tx];
    __syncthreads();
    const size_t rowoff = (size_t)blockIdx.z * HK;
    #pragma unroll
    for (int r = 0; r < 4; r++)
        dh[(rowoff + n0 + ty + r * 8) * KD + k0 + tx] = __float2half(t[tx][ty + r * 8]);
}

// ---------------------------------------------------------------------------
// V transpose per head from fp16 QKV buffer -> fp16 [(b*8+h)*512+d][t].
// ---------------------------------------------------------------------------
__global__ void vconvh(const __half* __restrict__ qv, __half* __restrict__ dh)
{
    __shared__ __half t[32][33];
    const int z = blockIdx.z, b = z >> 3, h = z & 7;
    const int t0 = blockIdx.x * 32, d0 = blockIdx.y * 32;
    const int tx = threadIdx.x, ty = threadIdx.y;
    #pragma unroll
    for (int r = 0; r < 4; r++) {
        const size_t si = (size_t)(b * SEQ + t0 + ty + r * 8) * QKVN
                        + 2 * HK + h * KD + d0 + tx;
        t[ty + r * 8][tx] = qv[si];
    }
    __syncthreads();
    #pragma unroll
    for (int r = 0; r < 4; r++) {
        const size_t o = ((size_t)z * KD + d0 + ty + r * 8) * SEQ + t0 + tx;
        dh[o] = t[tx][ty + r * 8];
    }
}

// ---------------------------------------------------------------------------
// Embedding + positional encoding.
// ---------------------------------------------------------------------------
__global__ void embed_k(const int* __restrict__ x, const float* __restrict__ W,
                        float* __restrict__ h, __half* __restrict__ hf)
{
    const int token = blockIdx.x;
    const int t  = token & (SEQ - 1);
    const int id = x[token];
    const int tid = threadIdx.x;
    #pragma unroll
    for (int u = 0; u < 2; u++) {
        const int c = tid + u * 256;
        const int j = c >> 1;
        const float ang = (float)t * expf(-(float)j * 0.07195578415606394f);
        const float p = (c & 1) ? cosf(ang) : sinf(ang);
        const float val = W[(size_t)id * KD + c] + p;
        const size_t o = (size_t)token * KD + c;
        h[o] = val;
        hf[o] = __float2half(val);
    }
}

// ---------------------------------------------------------------------------
// Causal softmax (scale folded), writes fp16 att.
// ---------------------------------------------------------------------------
__global__ void softmax_k(const float* __restrict__ att, __half* __restrict__ oh)
{
    const int q  = blockIdx.x;
    const int bh = blockIdx.y;
    const size_t base = ((size_t)bh * SEQ + q) * SEQ;
    const int tid = threadIdx.x;
    const float scale = 0.04419417382415922f;  // 1/sqrt(512)
    __shared__ float red[256];

    const float s0 = (tid       <= q) ? att[base + tid]       * scale : -3.4e38f;
    const float s1 = (tid + 256 <= q) ? att[base + tid + 256] * scale : -3.4e38f;
    red[tid] = fmaxf(s0, s1);
    __syncthreads();
    for (int o = 128; o; o >>= 1) {
        if (tid < o) red[tid] = fmaxf(red[tid], red[tid + o]);
        __syncthreads();
    }
    const float m = red[0];
    __syncthreads();
    const float v0 = (tid       <= q) ? expf(s0 - m) : 0.f;
    const float v1 = (tid + 256 <= q) ? expf(s1 - m) : 0.f;
    red[tid] = v0 + v1;
    __syncthreads();
    for (int o = 128; o; o >>= 1) {
        if (tid < o) red[tid] += red[tid + o];
        __syncthreads();
    }
    const float inv = 1.0f / red[0];
    oh[base + tid]       = __float2half(v0 * inv);
    oh[base + tid + 256] = __float2half(v1 * inv);
}

// ---------------------------------------------------------------------------
// Host-side launcher
// ---------------------------------------------------------------------------
struct GemmArgs {
    const __half *A, *B;
    const float* bias;
    float* C;
    __half* Ch;
    int M, N, K, lda, ldb, ldc;
    long aO, aI, bO, bI, cO, cI;
    int zdiv, batches, causal;
};

template<int EPI, int OUT>
static void launch_gemm(const GemmArgs& a)
{
    static bool attr_set = false;
    if (!attr_set) {
        cudaFuncSetAttribute(gemm_f16<EPI, OUT>,
                             cudaFuncAttributeMaxDynamicSharedMemorySize, GEMM_SMEM);
        attr_set = true;
    }
    dim3 grid(a.N / 128, a.M / 128, a.batches), block(256);
    gemm_f16<EPI, OUT><<<grid, block, GEMM_SMEM>>>(
        a.A, a.B, a.bias, a.C, a.Ch,
        a.M, a.N, a.K, a.lda, a.ldb, a.ldc,
        a.aO, a.aI, a.bO, a.bI, a.cO, a.cI, a.zdiv, a.causal);
}

extern "C" void kernel_launch(void* const* d_in, const int* in_sizes, int n_in,
                              void* d_out, int out_size)
{
    const int*   x        = (const int*)  d_in[0];
    const float* embed_W  = (const float*)d_in[1];
    const float* Wq       = (const float*)d_in[2];
    const float* Wk       = (const float*)d_in[3];
    const float* Wv       = (const float*)d_in[4];
    const float* Wu       = (const float*)d_in[5];
    const float* bu       = (const float*)d_in[6];
    const float* W1       = (const float*)d_in[7];
    const float* b1       = (const float*)d_in[8];
    const float* W2       = (const float*)d_in[9];
    const float* b2       = (const float*)d_in[10];
    const float* ln1_w    = (const float*)d_in[11];
    const float* ln1_b    = (const float*)d_in[12];
    const float* ln2_w    = (const float*)d_in[13];
    const float* ln2_b    = (const float*)d_in[14];
    const float* lnf_w    = (const float*)d_in[15];
    const float* lnf_b    = (const float*)d_in[16];
    const float* unembedW = (const float*)d_in[17];
    const float* unembedB = (const float*)d_in[18];
    float* out = (float*)d_out;

    float *h, *att;
    __half *hf, *wt, *qv, *vt, *as, *yf, *ff;
    cudaGetSymbolAddress((void**)&h,   g_h);
    cudaGetSymbolAddress((void**)&att, g_att);
    cudaGetSymbolAddress((void**)&hf,  g_hf);
    cudaGetSymbolAddress((void**)&wt,  g_wt);
    cudaGetSymbolAddress((void**)&qv,  g_qkv);
    cudaGetSymbolAddress((void**)&vt,  g_vt);
    cudaGetSymbolAddress((void**)&as,  g_as);
    cudaGetSymbolAddress((void**)&yf,  g_yf);
    cudaGetSymbolAddress((void**)&ff,  g_ff);

    embed_k<<<MTOK, 256>>>(x, embed_W, h, hf);

    const long atI = (long)SEQ * SEQ;          // 262144
    const long atO = (long)HEADS * atI;
    const long PS  = (long)MTOK * KD;          // split-K plane stride

    for (int i = 0; i < NBLK; i++) {
        const float* Wq_i = Wq + (size_t)i * KD * HK;
        const float* Wk_i = Wk + (size_t)i * KD * HK;
        const float* Wv_i = Wv + (size_t)i * KD * HK;
        const float* Wu_i = Wu + (size_t)i * HK * KD;
        const float* bu_i = bu + (size_t)i * KD;
        const float* W1_i = W1 + (size_t)i * KD * FF;
        const float* b1_i = b1 + (size_t)i * FF;
        const float* W2_i = W2 + (size_t)i * FF * KD;
        const float* b2_i = b2 + (size_t)i * KD;

        // fused QKV
        wconv3h<<<dim3(KD/32, HK/32, 3), dim3(32,8)>>>(Wq_i, Wk_i, Wv_i, wt);
        { GemmArgs a = {hf, wt, nullptr, nullptr, qv,
                        MTOK, QKVN, KD, KD, KD, QKVN, 0,0,0,0,0,0, 1, 1, 0};
          launch_gemm<0,2>(a); }

        // scores = Q @ K^T; skip upper-triangle tiles
        { GemmArgs a = {qv, qv + HK, nullptr, att, nullptr,
                        SEQ, SEQ, KD, QKVN, QKVN, SEQ,
                        (long)SEQ*QKVN, (long)KD, (long)SEQ*QKVN, (long)KD,
                        atO, atI, HEADS, NBH, 1};
          launch_gemm<0,0>(a); }

        softmax_k<<<dim3(SEQ, NBH), 256>>>(att, as);
        vconvh<<<dim3(16,16,NBH), dim3(32,8)>>>(qv, vt);

        // y = att @ V; truncate K per tile row
        { GemmArgs a = {as, vt, nullptr, nullptr, yf,
                        SEQ, KD, SEQ, SEQ, SEQ, HK,
                        atO, atI, atO, atI,
                        (long)SEQ*HK, (long)KD, HEADS, NBH, 2};
          launch_gemm<0,2>(a); }

        // proj: split-K=4 -> partial planes in att -> fused reduce+LN
        wconvh<<<dim3(HK/32, KD/32), dim3(32,8)>>>(Wu_i, wt, HK, KD);
        { GemmArgs a = {yf, wt, nullptr, att, nullptr,
                        MTOK, KD, 1024, HK, HK, KD,
                        1024, 0, 1024, 0, PS, 0, 1, 4, 0};
          launch_gemm<0,0>(a); }
        ln_red_k<<<MTOK, 256>>>(att, PS, bu_i, h, hf,
                                ln1_w + (size_t)i * KD, ln1_b + (size_t)i * KD);

        // ff = gelu(h @ W1 + b1) -> fp16
        wconvh<<<dim3(KD/32, FF/32), dim3(32,8)>>>(W1_i, wt, KD, FF);
        { GemmArgs a = {hf, wt, b1_i, nullptr, ff,
                        MTOK, FF, KD, KD, KD, FF, 0,0,0,0,0,0, 1, 1, 0};
          launch_gemm<2,2>(a); }

        // W2: split-K=4 -> partial planes -> fused reduce+LN
        wconvh<<<dim3(FF/32, KD/32), dim3(32,8)>>>(W2_i, wt, FF, KD);
        { GemmArgs a = {ff, wt, nullptr, att, nullptr,
                        MTOK, KD, 512, FF, FF, KD,
                        512, 0, 512, 0, PS, 0, 1, 4, 0};
          launch_gemm<0,0>(a); }
        ln_red_k<<<MTOK, 256>>>(att, PS, b2_i, h, hf,
                                ln2_w + (size_t)i * KD, ln2_b + (size_t)i * KD);
    }

    ln_k<<<MTOK, 256>>>(h, h, hf, lnf_w, lnf_b);

    // unembed
    wconvh<<<dim3(KD/32, VOCAB/32), dim3(32,8)>>>(unembedW, wt, KD, VOCAB);
    { GemmArgs a = {hf, wt, unembedB, out, nullptr,
                    MTOK, VOCAB, KD, KD, KD, VOCAB, 0,0,0,0,0,0, 1, 1, 0};
      launch_gemm<1,0>(a); }
}